// round 5
// baseline (speedup 1.0000x reference)
#include <cuda_runtime.h>
#include <math.h>

#define B 128
#define C 1024
#define DIN 1024
#define TWO_D 2048
#define NUM_CLASSES 10
#define ALPHA 1e-3f
#define GAMMA 1e-2f

#define BM 64
#define BN 64
#define BK 32
#define PAD 4
#define KSPLIT 4
#define KSLICE (TWO_D / KSPLIT)   // 512
#define NT (KSLICE / BK)          // 16 tiles

// Scratch (static device globals; no dynamic allocation)
__device__ float g_pmin[B];
__device__ float g_pmax[B];
__device__ float g_coded[B * TWO_D];
__device__ float g_den[C];
__device__ float g_part[KSPLIT][B][C];

// ---------------------------------------------------------------------------
// K1: per-batch-row min/max partials of x
// ---------------------------------------------------------------------------
__global__ void k_minmax_partial(const float* __restrict__ x) {
    int b = blockIdx.x;
    int t = threadIdx.x;  // 128
    const float* row = x + b * DIN;
    float mn = 1e30f, mx = -1e30f;
    #pragma unroll
    for (int i = 0; i < 2; i++) {
        float4 v = ((const float4*)row)[t + i * 128];
        mn = fminf(mn, fminf(fminf(v.x, v.y), fminf(v.z, v.w)));
        mx = fmaxf(mx, fmaxf(fmaxf(v.x, v.y), fmaxf(v.z, v.w)));
    }
    #pragma unroll
    for (int o = 16; o > 0; o >>= 1) {
        mn = fminf(mn, __shfl_xor_sync(0xffffffffu, mn, o));
        mx = fmaxf(mx, __shfl_xor_sync(0xffffffffu, mx, o));
    }
    __shared__ float smn[4], smx[4];
    if ((t & 31) == 0) { smn[t >> 5] = mn; smx[t >> 5] = mx; }
    __syncthreads();
    if (t == 0) {
        mn = smn[0]; mx = smx[0];
        #pragma unroll
        for (int w = 1; w < 4; w++) { mn = fminf(mn, smn[w]); mx = fmaxf(mx, smx[w]); }
        g_pmin[b] = mn;
        g_pmax[b] = mx;
    }
}

// ---------------------------------------------------------------------------
// K2: blocks [0,C): den[c] = alpha + rowsum(T[c]) + gamma*counts[c]
//     blocks [C,C+B): final minmax reduce (local) + complement-coded rows
// ---------------------------------------------------------------------------
__global__ void k_prep(const float* __restrict__ x,
                       const float* __restrict__ T,
                       const int* __restrict__ counts) {
    int blk = blockIdx.x;
    int t = threadIdx.x;  // 256
    if (blk < C) {
        const float4* row = (const float4*)(T + (size_t)blk * TWO_D);
        float s = 0.0f;
        #pragma unroll
        for (int i = 0; i < 2; i++) {
            float4 v = row[t + i * 256];
            s += (v.x + v.y) + (v.z + v.w);
        }
        #pragma unroll
        for (int o = 16; o > 0; o >>= 1)
            s += __shfl_xor_sync(0xffffffffu, s, o);
        __shared__ float ss[8];
        if ((t & 31) == 0) ss[t >> 5] = s;
        __syncthreads();
        if (t == 0) {
            #pragma unroll
            for (int w = 1; w < 8; w++) s += ss[w];
            g_den[blk] = ALPHA + s + GAMMA * (float)counts[blk];
        }
    } else {
        int b = blk - C;
        __shared__ float smn[4], smx[4];
        float mn = 1e30f, mx = -1e30f;
        if (t < 128) {
            mn = g_pmin[t];
            mx = g_pmax[t];
            #pragma unroll
            for (int o = 16; o > 0; o >>= 1) {
                mn = fminf(mn, __shfl_xor_sync(0xffffffffu, mn, o));
                mx = fmaxf(mx, __shfl_xor_sync(0xffffffffu, mx, o));
            }
            if ((t & 31) == 0) { smn[t >> 5] = mn; smx[t >> 5] = mx; }
        }
        __syncthreads();
        mn = fminf(fminf(smn[0], smn[1]), fminf(smn[2], smn[3]));
        mx = fmaxf(fmaxf(smx[0], smx[1]), fmaxf(smx[2], smx[3]));
        float sc = 1.0f / (mx - mn + 1e-10f);

        const float* xr = x + (size_t)b * DIN;
        float* cr = g_coded + (size_t)b * TWO_D;
        #pragma unroll
        for (int i = 0; i < 4; i++) {
            int k = t + i * 256;
            float xn = (xr[k] - mn) * sc;
            cr[k] = xn;
            cr[DIN + k] = 1.0f - xn;
        }
    }
}

// ---------------------------------------------------------------------------
// K3: min-sum "GEMM". BM=BN=64, BK=32, 256 threads (16x16), TM=TN=4.
// grid = (C/BN=16, B/BM=2, KSPLIT=4) = 128 CTAs = one full wave.
// Double-buffered smem, one __syncthreads per tile.
// ---------------------------------------------------------------------------
__global__ void __launch_bounds__(256) k_choice(const float* __restrict__ T) {
    __shared__ float sA[2][BK][BM + PAD];
    __shared__ float sB[2][BK][BN + PAD];

    int tid = threadIdx.x;
    int tx = tid & 15;       // n-group
    int ty = tid >> 4;       // m-group
    int mbase = blockIdx.y * BM;
    int nbase = blockIdx.x * BN;
    int k0base = blockIdx.z * KSLICE;

    int lrow = tid >> 3;     // 0..31
    int lkv = tid & 7;       // float4 index within BK

    const float4* pa0 = (const float4*)&g_coded[(size_t)(mbase + lrow) * TWO_D + k0base + lkv * 4];
    const float4* pa1 = (const float4*)&g_coded[(size_t)(mbase + lrow + 32) * TWO_D + k0base + lkv * 4];
    const float4* pb0 = (const float4*)&T[(size_t)(nbase + lrow) * TWO_D + k0base + lkv * 4];
    const float4* pb1 = (const float4*)&T[(size_t)(nbase + lrow + 32) * TWO_D + k0base + lkv * 4];
    const int step = BK / 4;   // float4 stride per tile

    float acc[4][4];
    #pragma unroll
    for (int i = 0; i < 4; i++)
        #pragma unroll
        for (int j = 0; j < 4; j++) acc[i][j] = 0.0f;

    // prefetch tile 0
    float4 va0 = pa0[0], va1 = pa1[0], vb0 = pb0[0], vb1 = pb1[0];
    int buf = 0;
    {   // store tile 0
        int kc = lkv * 4;
        sA[0][kc + 0][lrow] = va0.x; sA[0][kc + 1][lrow] = va0.y;
        sA[0][kc + 2][lrow] = va0.z; sA[0][kc + 3][lrow] = va0.w;
        sA[0][kc + 0][lrow + 32] = va1.x; sA[0][kc + 1][lrow + 32] = va1.y;
        sA[0][kc + 2][lrow + 32] = va1.z; sA[0][kc + 3][lrow + 32] = va1.w;
        sB[0][kc + 0][lrow] = vb0.x; sB[0][kc + 1][lrow] = vb0.y;
        sB[0][kc + 2][lrow] = vb0.z; sB[0][kc + 3][lrow] = vb0.w;
        sB[0][kc + 0][lrow + 32] = vb1.x; sB[0][kc + 1][lrow + 32] = vb1.y;
        sB[0][kc + 2][lrow + 32] = vb1.z; sB[0][kc + 3][lrow + 32] = vb1.w;
    }
    __syncthreads();

    for (int t = 0; t < NT; t++) {
        if (t + 1 < NT) {   // prefetch next tile into regs (overlaps compute)
            int o = (t + 1) * step;
            va0 = pa0[o]; va1 = pa1[o]; vb0 = pb0[o]; vb1 = pb1[o];
        }
        #pragma unroll
        for (int k = 0; k < BK; k++) {
            float4 a = *(const float4*)&sA[buf][k][ty * 4];
            float4 bb = *(const float4*)&sB[buf][k][tx * 4];
            float av[4] = {a.x, a.y, a.z, a.w};
            float bv[4] = {bb.x, bb.y, bb.z, bb.w};
            #pragma unroll
            for (int i = 0; i < 4; i++)
                #pragma unroll
                for (int j = 0; j < 4; j++)
                    acc[i][j] += fminf(av[i], bv[j]);
        }
        if (t + 1 < NT) {
            int nb = buf ^ 1;
            int kc = lkv * 4;
            sA[nb][kc + 0][lrow] = va0.x; sA[nb][kc + 1][lrow] = va0.y;
            sA[nb][kc + 2][lrow] = va0.z; sA[nb][kc + 3][lrow] = va0.w;
            sA[nb][kc + 0][lrow + 32] = va1.x; sA[nb][kc + 1][lrow + 32] = va1.y;
            sA[nb][kc + 2][lrow + 32] = va1.z; sA[nb][kc + 3][lrow + 32] = va1.w;
            sB[nb][kc + 0][lrow] = vb0.x; sB[nb][kc + 1][lrow] = vb0.y;
            sB[nb][kc + 2][lrow] = vb0.z; sB[nb][kc + 3][lrow] = vb0.w;
            sB[nb][kc + 0][lrow + 32] = vb1.x; sB[nb][kc + 1][lrow + 32] = vb1.y;
            sB[nb][kc + 2][lrow + 32] = vb1.z; sB[nb][kc + 3][lrow + 32] = vb1.w;
            __syncthreads();
            buf = nb;
        }
    }

    int b0 = mbase + ty * 4;
    int c0 = nbase + tx * 4;
    #pragma unroll
    for (int i = 0; i < 4; i++) {
        float4 v = make_float4(acc[i][0], acc[i][1], acc[i][2], acc[i][3]);
        *(float4*)&g_part[blockIdx.z][b0 + i][c0] = v;
    }
}

// ---------------------------------------------------------------------------
// K4: per batch row (1024 threads, 1 category each): combine K-slices,
// divide by den, masked argmax (first-index tie), per-label sums,
// write one_hot(pred) * label_sums. committed is int32.
// ---------------------------------------------------------------------------
__global__ void __launch_bounds__(1024) k_epilogue(const int* __restrict__ committed,
                                                   const int* __restrict__ labels,
                                                   float* __restrict__ out) {
    int b = blockIdx.x;
    int t = threadIdx.x;        // 0..1023 == category index
    int lane = t & 31;
    int wid = t >> 5;
    __shared__ float bins[NUM_CLASSES];
    __shared__ float wval[32];
    __shared__ int widx[32];

    if (t < NUM_CLASSES) bins[t] = 0.0f;
    __syncthreads();

    float num = 0.0f;
    #pragma unroll
    for (int s = 0; s < KSPLIT; s++) num += g_part[s][b][t];
    float v = num / g_den[t];
    bool com = (committed[t] != 0);
    float best = com ? v : -INFINITY;
    int bidx = t;
    if (com) atomicAdd(&bins[labels[t]], v);

    // warp argmax, first-index on tie
    #pragma unroll
    for (int o = 16; o > 0; o >>= 1) {
        float ov = __shfl_xor_sync(0xffffffffu, best, o);
        int oi = __shfl_xor_sync(0xffffffffu, bidx, o);
        if (ov > best || (ov == best && oi < bidx)) { best = ov; bidx = oi; }
    }
    if (lane == 0) { wval[wid] = best; widx[wid] = bidx; }
    __syncthreads();

    if (wid == 0) {
        best = wval[lane];
        bidx = widx[lane];
        #pragma unroll
        for (int o = 16; o > 0; o >>= 1) {
            float ov = __shfl_xor_sync(0xffffffffu, best, o);
            int oi = __shfl_xor_sync(0xffffffffu, bidx, o);
            if (ov > best || (ov == best && oi < bidx)) { best = ov; bidx = oi; }
        }
        if (lane == 0) widx[0] = bidx;
    }
    __syncthreads();

    if (t < NUM_CLASSES) {
        int pl = labels[widx[0]];
        out[b * NUM_CLASSES + t] = (t == pl) ? bins[t] : 0.0f;
    }
}

// ---------------------------------------------------------------------------
extern "C" void kernel_launch(void* const* d_in, const int* in_sizes, int n_in,
                              void* d_out, int out_size) {
    const float* x = (const float*)d_in[0];
    const float* T = (const float*)d_in[1];
    const int* committed = (const int*)d_in[2];
    const int* labels = (const int*)d_in[3];
    const int* counts = (const int*)d_in[4];
    float* out = (float*)d_out;

    k_minmax_partial<<<B, 128>>>(x);
    k_prep<<<C + B, 256>>>(x, T, counts);
    dim3 g3(C / BN, B / BM, KSPLIT);
    k_choice<<<g3, 256>>>(T);
    k_epilogue<<<B, 1024>>>(committed, labels, out);
}

// round 6
// speedup vs baseline: 1.0785x; 1.0785x over previous
#include <cuda_runtime.h>
#include <math.h>

#define B 128
#define C 1024
#define DIN 1024
#define TWO_D 2048
#define NUM_CLASSES 10
#define ALPHA 1e-3f
#define GAMMA 1e-2f

#define BM 64
#define BN 128
#define BK 32
#define PAD 4
#define KSPLIT 8
#define KSLICE (TWO_D / KSPLIT)   // 256
#define NT (KSLICE / BK)          // 8 tiles

// Scratch (static device globals; no dynamic allocation)
__device__ float g_pmin[B];
__device__ float g_pmax[B];
__device__ float g_coded[B * TWO_D];
__device__ float g_den[C];
__device__ float g_part[KSPLIT][B][C];

// ---------------------------------------------------------------------------
// K1: per-batch-row min/max partials of x
// ---------------------------------------------------------------------------
__global__ void k_minmax_partial(const float* __restrict__ x) {
    int b = blockIdx.x;
    int t = threadIdx.x;  // 128
    const float* row = x + b * DIN;
    float mn = 1e30f, mx = -1e30f;
    #pragma unroll
    for (int i = 0; i < 2; i++) {
        float4 v = ((const float4*)row)[t + i * 128];
        mn = fminf(mn, fminf(fminf(v.x, v.y), fminf(v.z, v.w)));
        mx = fmaxf(mx, fmaxf(fmaxf(v.x, v.y), fmaxf(v.z, v.w)));
    }
    #pragma unroll
    for (int o = 16; o > 0; o >>= 1) {
        mn = fminf(mn, __shfl_xor_sync(0xffffffffu, mn, o));
        mx = fmaxf(mx, __shfl_xor_sync(0xffffffffu, mx, o));
    }
    __shared__ float smn[4], smx[4];
    if ((t & 31) == 0) { smn[t >> 5] = mn; smx[t >> 5] = mx; }
    __syncthreads();
    if (t == 0) {
        mn = smn[0]; mx = smx[0];
        #pragma unroll
        for (int w = 1; w < 4; w++) { mn = fminf(mn, smn[w]); mx = fmaxf(mx, smx[w]); }
        g_pmin[b] = mn;
        g_pmax[b] = mx;
    }
}

// ---------------------------------------------------------------------------
// K2: blocks [0,C): den[c] = alpha + rowsum(T[c]) + gamma*counts[c]
//     blocks [C,C+B): final minmax reduce (local) + complement-coded rows
// ---------------------------------------------------------------------------
__global__ void k_prep(const float* __restrict__ x,
                       const float* __restrict__ T,
                       const int* __restrict__ counts) {
    int blk = blockIdx.x;
    int t = threadIdx.x;  // 256
    if (blk < C) {
        const float4* row = (const float4*)(T + (size_t)blk * TWO_D);
        float s = 0.0f;
        #pragma unroll
        for (int i = 0; i < 2; i++) {
            float4 v = row[t + i * 256];
            s += (v.x + v.y) + (v.z + v.w);
        }
        #pragma unroll
        for (int o = 16; o > 0; o >>= 1)
            s += __shfl_xor_sync(0xffffffffu, s, o);
        __shared__ float ss[8];
        if ((t & 31) == 0) ss[t >> 5] = s;
        __syncthreads();
        if (t == 0) {
            #pragma unroll
            for (int w = 1; w < 8; w++) s += ss[w];
            g_den[blk] = ALPHA + s + GAMMA * (float)counts[blk];
        }
    } else {
        int b = blk - C;
        __shared__ float smn[4], smx[4];
        float mn = 1e30f, mx = -1e30f;
        if (t < 128) {
            mn = g_pmin[t];
            mx = g_pmax[t];
            #pragma unroll
            for (int o = 16; o > 0; o >>= 1) {
                mn = fminf(mn, __shfl_xor_sync(0xffffffffu, mn, o));
                mx = fmaxf(mx, __shfl_xor_sync(0xffffffffu, mx, o));
            }
            if ((t & 31) == 0) { smn[t >> 5] = mn; smx[t >> 5] = mx; }
        }
        __syncthreads();
        mn = fminf(fminf(smn[0], smn[1]), fminf(smn[2], smn[3]));
        mx = fmaxf(fmaxf(smx[0], smx[1]), fmaxf(smx[2], smx[3]));
        float sc = 1.0f / (mx - mn + 1e-10f);

        const float* xr = x + (size_t)b * DIN;
        float* cr = g_coded + (size_t)b * TWO_D;
        #pragma unroll
        for (int i = 0; i < 4; i++) {
            int k = t + i * 256;
            float xn = (xr[k] - mn) * sc;
            cr[k] = xn;
            cr[DIN + k] = 1.0f - xn;
        }
    }
}

// ---------------------------------------------------------------------------
// K3: min-sum "GEMM". BM=64, BN=128, BK=32, 512 threads (32x16), TM=TN=4.
// grid = (C/BN=8, B/BM=2, KSPLIT=8) = 128 CTAs = one wave, 4 warps/SMSP.
// Single smem buffer; register prefetch of next tile overlaps compute.
// ---------------------------------------------------------------------------
__global__ void __launch_bounds__(512) k_choice(const float* __restrict__ T) {
    __shared__ float sA[BK][BM + PAD];   // 32 x 68
    __shared__ float sB[BK][BN + PAD];   // 32 x 132

    int tid = threadIdx.x;
    int tx = tid & 31;       // n-group: 0..31 -> n0 = tx*4 (BN=128)
    int ty = tid >> 5;       // m-group: 0..15 -> m0 = ty*4 (BM=64)
    int mbase = blockIdx.y * BM;
    int nbase = blockIdx.x * BN;
    int k0 = blockIdx.z * KSLICE;

    int ra = tid >> 3;       // 0..63
    int kv = tid & 7;        // float4 index within BK

    const float4* pA  = (const float4*)&g_coded[(size_t)(mbase + ra) * TWO_D + k0 + kv * 4];
    const float4* pB0 = (const float4*)&T[(size_t)(nbase + ra) * TWO_D + k0 + kv * 4];
    const float4* pB1 = (const float4*)&T[(size_t)(nbase + ra + 64) * TWO_D + k0 + kv * 4];
    const int step = BK / 4;   // 8 float4 per tile

    float acc[4][4];
    #pragma unroll
    for (int i = 0; i < 4; i++)
        #pragma unroll
        for (int j = 0; j < 4; j++) acc[i][j] = 0.0f;

    // prefetch tile 0
    float4 va = pA[0], vb0 = pB0[0], vb1 = pB1[0];

    for (int tt = 0; tt < NT; tt++) {
        __syncthreads();   // previous compute done before overwriting smem
        {
            int kc = kv * 4;
            sA[kc + 0][ra] = va.x; sA[kc + 1][ra] = va.y;
            sA[kc + 2][ra] = va.z; sA[kc + 3][ra] = va.w;
            sB[kc + 0][ra] = vb0.x; sB[kc + 1][ra] = vb0.y;
            sB[kc + 2][ra] = vb0.z; sB[kc + 3][ra] = vb0.w;
            sB[kc + 0][ra + 64] = vb1.x; sB[kc + 1][ra + 64] = vb1.y;
            sB[kc + 2][ra + 64] = vb1.z; sB[kc + 3][ra + 64] = vb1.w;
        }
        __syncthreads();
        if (tt + 1 < NT) {   // prefetch next tile (LDG latency overlaps compute)
            int o = (tt + 1) * step;
            va = pA[o]; vb0 = pB0[o]; vb1 = pB1[o];
        }
        #pragma unroll
        for (int k = 0; k < BK; k++) {
            float4 a = *(const float4*)&sA[k][ty * 4];
            float4 bb = *(const float4*)&sB[k][tx * 4];
            float av[4] = {a.x, a.y, a.z, a.w};
            float bv[4] = {bb.x, bb.y, bb.z, bb.w};
            #pragma unroll
            for (int i = 0; i < 4; i++)
                #pragma unroll
                for (int j = 0; j < 4; j++)
                    acc[i][j] += fminf(av[i], bv[j]);
        }
    }

    int b0 = mbase + ty * 4;
    int c0 = nbase + tx * 4;
    #pragma unroll
    for (int i = 0; i < 4; i++) {
        float4 v = make_float4(acc[i][0], acc[i][1], acc[i][2], acc[i][3]);
        *(float4*)&g_part[blockIdx.z][b0 + i][c0] = v;
    }
}

// ---------------------------------------------------------------------------
// K4: per batch row (1024 threads, 1 category each): combine K-slices,
// divide by den, masked argmax (first-index tie), per-label sums via
// warp shuffle reductions (no contended atomics), write one_hot * sums.
// committed is int32.
// ---------------------------------------------------------------------------
__global__ void __launch_bounds__(1024) k_epilogue(const int* __restrict__ committed,
                                                   const int* __restrict__ labels,
                                                   float* __restrict__ out) {
    int b = blockIdx.x;
    int t = threadIdx.x;        // 0..1023 == category index
    int lane = t & 31;
    int wid = t >> 5;
    __shared__ float bins[NUM_CLASSES];
    __shared__ float wval[32];
    __shared__ int widx[32];

    if (t < NUM_CLASSES) bins[t] = 0.0f;
    __syncthreads();

    float num = 0.0f;
    #pragma unroll
    for (int s = 0; s < KSPLIT; s++) num += g_part[s][b][t];
    float v = num / g_den[t];
    bool com = (committed[t] != 0);
    int lab = labels[t];
    float vz = com ? v : 0.0f;

    // per-class warp sums: 10 shuffle reductions, one atomic per class per warp
    #pragma unroll
    for (int cls = 0; cls < NUM_CLASSES; cls++) {
        float m = (lab == cls) ? vz : 0.0f;
        #pragma unroll
        for (int o = 16; o > 0; o >>= 1)
            m += __shfl_xor_sync(0xffffffffu, m, o);
        if (lane == 0) atomicAdd(&bins[cls], m);
    }

    // warp argmax, first-index on tie
    float best = com ? v : -INFINITY;
    int bidx = t;
    #pragma unroll
    for (int o = 16; o > 0; o >>= 1) {
        float ov = __shfl_xor_sync(0xffffffffu, best, o);
        int oi = __shfl_xor_sync(0xffffffffu, bidx, o);
        if (ov > best || (ov == best && oi < bidx)) { best = ov; bidx = oi; }
    }
    if (lane == 0) { wval[wid] = best; widx[wid] = bidx; }
    __syncthreads();

    if (wid == 0) {
        best = wval[lane];
        bidx = widx[lane];
        #pragma unroll
        for (int o = 16; o > 0; o >>= 1) {
            float ov = __shfl_xor_sync(0xffffffffu, best, o);
            int oi = __shfl_xor_sync(0xffffffffu, bidx, o);
            if (ov > best || (ov == best && oi < bidx)) { best = ov; bidx = oi; }
        }
        if (lane == 0) widx[0] = bidx;
    }
    __syncthreads();

    if (t < NUM_CLASSES) {
        int pl = labels[widx[0]];
        out[b * NUM_CLASSES + t] = (t == pl) ? bins[t] : 0.0f;
    }
}

// ---------------------------------------------------------------------------
extern "C" void kernel_launch(void* const* d_in, const int* in_sizes, int n_in,
                              void* d_out, int out_size) {
    const float* x = (const float*)d_in[0];
    const float* T = (const float*)d_in[1];
    const int* committed = (const int*)d_in[2];
    const int* labels = (const int*)d_in[3];
    const int* counts = (const int*)d_in[4];
    float* out = (float*)d_out;

    k_minmax_partial<<<B, 128>>>(x);
    k_prep<<<C + B, 256>>>(x, T, counts);
    dim3 g3(C / BN, B / BM, KSPLIT);
    k_choice<<<g3, 512>>>(T);
    k_epilogue<<<B, 1024>>>(committed, labels, out);
}

// round 7
// speedup vs baseline: 1.1174x; 1.0361x over previous
#include <cuda_runtime.h>
#include <math.h>

#define B 128
#define C 1024
#define DIN 1024
#define TWO_D 2048
#define NUM_CLASSES 10
#define ALPHA 1e-3f
#define GAMMA 1e-2f

#define BM 64
#define BN 128
#define BK 32
#define PAD 4
#define KSPLIT 8
#define KSLICE (TWO_D / KSPLIT)   // 256
#define NT (KSLICE / BK)          // 8 tiles

#define SA_STRIDE (BM + PAD)              // 68
#define SB_STRIDE (BN + PAD)              // 132
#define SA_BUF (BK * SA_STRIDE)           // 2176 floats
#define SB_BUF (BK * SB_STRIDE)           // 4224 floats
#define SMEM_FLOATS (2 * SA_BUF + 2 * SB_BUF)
#define SMEM_BYTES (SMEM_FLOATS * 4)      // 51200 B

// Scratch (static device globals; no dynamic allocation)
__device__ float g_pmin[B];
__device__ float g_pmax[B];
__device__ float g_coded[B * TWO_D];
__device__ float g_den[C];
__device__ float g_part[KSPLIT][B][C];
__device__ float g_choice[B][C];

// ---------------------------------------------------------------------------
// K1: per-batch-row min/max partials of x
// ---------------------------------------------------------------------------
__global__ void k_minmax_partial(const float* __restrict__ x) {
    int b = blockIdx.x;
    int t = threadIdx.x;  // 128
    const float* row = x + b * DIN;
    float mn = 1e30f, mx = -1e30f;
    #pragma unroll
    for (int i = 0; i < 2; i++) {
        float4 v = ((const float4*)row)[t + i * 128];
        mn = fminf(mn, fminf(fminf(v.x, v.y), fminf(v.z, v.w)));
        mx = fmaxf(mx, fmaxf(fmaxf(v.x, v.y), fmaxf(v.z, v.w)));
    }
    #pragma unroll
    for (int o = 16; o > 0; o >>= 1) {
        mn = fminf(mn, __shfl_xor_sync(0xffffffffu, mn, o));
        mx = fmaxf(mx, __shfl_xor_sync(0xffffffffu, mx, o));
    }
    __shared__ float smn[4], smx[4];
    if ((t & 31) == 0) { smn[t >> 5] = mn; smx[t >> 5] = mx; }
    __syncthreads();
    if (t == 0) {
        mn = smn[0]; mx = smx[0];
        #pragma unroll
        for (int w = 1; w < 4; w++) { mn = fminf(mn, smn[w]); mx = fmaxf(mx, smx[w]); }
        g_pmin[b] = mn;
        g_pmax[b] = mx;
    }
}

// ---------------------------------------------------------------------------
// K2: blocks [0,C): den[c] = alpha + rowsum(T[c]) + gamma*counts[c]
//     blocks [C,C+B): final minmax reduce (local) + complement-coded rows
// ---------------------------------------------------------------------------
__global__ void k_prep(const float* __restrict__ x,
                       const float* __restrict__ T,
                       const int* __restrict__ counts) {
    int blk = blockIdx.x;
    int t = threadIdx.x;  // 256
    if (blk < C) {
        const float4* row = (const float4*)(T + (size_t)blk * TWO_D);
        float s = 0.0f;
        #pragma unroll
        for (int i = 0; i < 2; i++) {
            float4 v = row[t + i * 256];
            s += (v.x + v.y) + (v.z + v.w);
        }
        #pragma unroll
        for (int o = 16; o > 0; o >>= 1)
            s += __shfl_xor_sync(0xffffffffu, s, o);
        __shared__ float ss[8];
        if ((t & 31) == 0) ss[t >> 5] = s;
        __syncthreads();
        if (t == 0) {
            #pragma unroll
            for (int w = 1; w < 8; w++) s += ss[w];
            g_den[blk] = ALPHA + s + GAMMA * (float)counts[blk];
        }
    } else {
        int b = blk - C;
        __shared__ float smn[4], smx[4];
        float mn = 1e30f, mx = -1e30f;
        if (t < 128) {
            mn = g_pmin[t];
            mx = g_pmax[t];
            #pragma unroll
            for (int o = 16; o > 0; o >>= 1) {
                mn = fminf(mn, __shfl_xor_sync(0xffffffffu, mn, o));
                mx = fmaxf(mx, __shfl_xor_sync(0xffffffffu, mx, o));
            }
            if ((t & 31) == 0) { smn[t >> 5] = mn; smx[t >> 5] = mx; }
        }
        __syncthreads();
        mn = fminf(fminf(smn[0], smn[1]), fminf(smn[2], smn[3]));
        mx = fmaxf(fmaxf(smx[0], smx[1]), fmaxf(smx[2], smx[3]));
        float sc = 1.0f / (mx - mn + 1e-10f);

        const float* xr = x + (size_t)b * DIN;
        float* cr = g_coded + (size_t)b * TWO_D;
        #pragma unroll
        for (int i = 0; i < 4; i++) {
            int k = t + i * 256;
            float xn = (xr[k] - mn) * sc;
            cr[k] = xn;
            cr[DIN + k] = 1.0f - xn;
        }
    }
}

// ---------------------------------------------------------------------------
// K3: min-sum "GEMM". BM=64, BN=128, BK=32, 512 threads (32x16), TM=TN=4.
// grid = (8, 2, 8) = 128 CTAs = one wave, 4 warps/SMSP.
// Double-buffered dynamic smem, ONE __syncthreads per tile.
// ---------------------------------------------------------------------------
__global__ void __launch_bounds__(512) k_choice(const float* __restrict__ T) {
    extern __shared__ float sm[];
    float* sA = sm;                  // [2][BK][BM+PAD]
    float* sB = sm + 2 * SA_BUF;     // [2][BK][BN+PAD]

    int tid = threadIdx.x;
    int tx = tid & 31;       // n-group -> n0 = tx*4
    int ty = tid >> 5;       // m-group -> m0 = ty*4
    int mbase = blockIdx.y * BM;
    int nbase = blockIdx.x * BN;
    int k0 = blockIdx.z * KSLICE;

    int ra = tid >> 3;       // 0..63
    int kv = tid & 7;        // float4 index within BK

    const float4* pA  = (const float4*)&g_coded[(size_t)(mbase + ra) * TWO_D + k0 + kv * 4];
    const float4* pB0 = (const float4*)&T[(size_t)(nbase + ra) * TWO_D + k0 + kv * 4];
    const float4* pB1 = (const float4*)&T[(size_t)(nbase + ra + 64) * TWO_D + k0 + kv * 4];

    float acc[4][4];
    #pragma unroll
    for (int i = 0; i < 4; i++)
        #pragma unroll
        for (int j = 0; j < 4; j++) acc[i][j] = 0.0f;

    // prefetch + store tile 0 into buffer 0
    float4 va = pA[0], vb0 = pB0[0], vb1 = pB1[0];
    {
        int kc = kv * 4;
        float* a = sA + kc * SA_STRIDE;
        a[ra] = va.x; a[SA_STRIDE + ra] = va.y;
        a[2 * SA_STRIDE + ra] = va.z; a[3 * SA_STRIDE + ra] = va.w;
        float* bp = sB + kc * SB_STRIDE;
        bp[ra] = vb0.x; bp[SB_STRIDE + ra] = vb0.y;
        bp[2 * SB_STRIDE + ra] = vb0.z; bp[3 * SB_STRIDE + ra] = vb0.w;
        bp[ra + 64] = vb1.x; bp[SB_STRIDE + ra + 64] = vb1.y;
        bp[2 * SB_STRIDE + ra + 64] = vb1.z; bp[3 * SB_STRIDE + ra + 64] = vb1.w;
    }
    __syncthreads();

    int buf = 0;
    for (int tt = 0; tt < NT; tt++) {
        if (tt + 1 < NT) {   // prefetch next tile (overlaps compute below)
            int o = (tt + 1) * (BK / 4);
            va = pA[o]; vb0 = pB0[o]; vb1 = pB1[o];
        }
        const float* cA = sA + buf * SA_BUF + ty * 4;
        const float* cB = sB + buf * SB_BUF + tx * 4;
        #pragma unroll
        for (int k = 0; k < BK; k++) {
            float4 a = *(const float4*)(cA + k * SA_STRIDE);
            float4 bb = *(const float4*)(cB + k * SB_STRIDE);
            float av[4] = {a.x, a.y, a.z, a.w};
            float bv[4] = {bb.x, bb.y, bb.z, bb.w};
            #pragma unroll
            for (int i = 0; i < 4; i++)
                #pragma unroll
                for (int j = 0; j < 4; j++)
                    acc[i][j] += fminf(av[i], bv[j]);
        }
        if (tt + 1 < NT) {
            int nb = buf ^ 1;
            int kc = kv * 4;
            float* a = sA + nb * SA_BUF + kc * SA_STRIDE;
            a[ra] = va.x; a[SA_STRIDE + ra] = va.y;
            a[2 * SA_STRIDE + ra] = va.z; a[3 * SA_STRIDE + ra] = va.w;
            float* bp = sB + nb * SB_BUF + kc * SB_STRIDE;
            bp[ra] = vb0.x; bp[SB_STRIDE + ra] = vb0.y;
            bp[2 * SB_STRIDE + ra] = vb0.z; bp[3 * SB_STRIDE + ra] = vb0.w;
            bp[ra + 64] = vb1.x; bp[SB_STRIDE + ra + 64] = vb1.y;
            bp[2 * SB_STRIDE + ra + 64] = vb1.z; bp[3 * SB_STRIDE + ra + 64] = vb1.w;
            __syncthreads();
            buf = nb;
        }
    }

    int b0 = mbase + ty * 4;
    int c0 = nbase + tx * 4;
    #pragma unroll
    for (int i = 0; i < 4; i++) {
        float4 v = make_float4(acc[i][0], acc[i][1], acc[i][2], acc[i][3]);
        *(float4*)&g_part[blockIdx.z][b0 + i][c0] = v;
    }
}

// ---------------------------------------------------------------------------
// K4: fold KSPLIT slices + divide by den. grid (4, B) x 256 -> 512 CTAs
// of latency-hiding parallelism for the scattered g_part traversal.
// ---------------------------------------------------------------------------
__global__ void k_reduce() {
    int c = blockIdx.x * 256 + threadIdx.x;
    int b = blockIdx.y;
    float num = 0.0f;
    #pragma unroll
    for (int s = 0; s < KSPLIT; s++) num += g_part[s][b][c];
    g_choice[b][c] = num / g_den[c];
}

// ---------------------------------------------------------------------------
// K5: per batch row (1024 threads, 1 category each): masked argmax
// (first-index tie), per-label sums via per-warp smem rows, one-hot output.
// committed is int32.
// ---------------------------------------------------------------------------
__global__ void __launch_bounds__(1024) k_final(const int* __restrict__ committed,
                                                const int* __restrict__ labels,
                                                float* __restrict__ out) {
    int b = blockIdx.x;
    int t = threadIdx.x;        // 0..1023 == category index
    int lane = t & 31;
    int wid = t >> 5;
    __shared__ float sbins[32][NUM_CLASSES];
    __shared__ float bins[NUM_CLASSES];
    __shared__ float wval[32];
    __shared__ int widx[32];

    if (lane < NUM_CLASSES) sbins[wid][lane] = 0.0f;
    __syncthreads();

    float v = g_choice[b][t];
    bool com = (committed[t] != 0);
    int lab = labels[t];
    if (com) atomicAdd(&sbins[wid][lab], v);

    // warp argmax, first-index on tie
    float best = com ? v : -INFINITY;
    int bidx = t;
    #pragma unroll
    for (int o = 16; o > 0; o >>= 1) {
        float ov = __shfl_xor_sync(0xffffffffu, best, o);
        int oi = __shfl_xor_sync(0xffffffffu, bidx, o);
        if (ov > best || (ov == best && oi < bidx)) { best = ov; bidx = oi; }
    }
    if (lane == 0) { wval[wid] = best; widx[wid] = bidx; }
    __syncthreads();

    if (wid == 0) {
        best = wval[lane];
        bidx = widx[lane];
        #pragma unroll
        for (int o = 16; o > 0; o >>= 1) {
            float ov = __shfl_xor_sync(0xffffffffu, best, o);
            int oi = __shfl_xor_sync(0xffffffffu, bidx, o);
            if (ov > best || (ov == best && oi < bidx)) { best = ov; bidx = oi; }
        }
        if (lane == 0) widx[0] = bidx;
    } else if (wid == 1 && lane < NUM_CLASSES) {
        float s = 0.0f;
        #pragma unroll
        for (int w = 0; w < 32; w++) s += sbins[w][lane];
        bins[lane] = s;
    }
    __syncthreads();

    if (t < NUM_CLASSES) {
        int pl = labels[widx[0]];
        out[b * NUM_CLASSES + t] = (t == pl) ? bins[t] : 0.0f;
    }
}

// ---------------------------------------------------------------------------
extern "C" void kernel_launch(void* const* d_in, const int* in_sizes, int n_in,
                              void* d_out, int out_size) {
    const float* x = (const float*)d_in[0];
    const float* T = (const float*)d_in[1];
    const int* committed = (const int*)d_in[2];
    const int* labels = (const int*)d_in[3];
    const int* counts = (const int*)d_in[4];
    float* out = (float*)d_out;

    cudaFuncSetAttribute(k_choice, cudaFuncAttributeMaxDynamicSharedMemorySize,
                         SMEM_BYTES);

    k_minmax_partial<<<B, 128>>>(x);
    k_prep<<<C + B, 256>>>(x, T, counts);
    dim3 g3(C / BN, B / BM, KSPLIT);
    k_choice<<<g3, 512, SMEM_BYTES>>>(T);
    dim3 g4(C / 256, B);
    k_reduce<<<g4, 256>>>();
    k_final<<<B, 1024>>>(committed, labels, out);
}

// round 9
// speedup vs baseline: 1.1235x; 1.0054x over previous
#include <cuda_runtime.h>
#include <math.h>

#define B 128
#define C 1024
#define DIN 1024
#define TWO_D 2048
#define NUM_CLASSES 10
#define ALPHA 1e-3f
#define GAMMA 1e-2f

#define BM 64
#define BN 128
#define BK 32
#define PAD 4
#define KSPLIT 8
#define KSLICE (TWO_D / KSPLIT)   // 256
#define NT (KSLICE / BK)          // 8 tiles

#define SA_STRIDE (BM + PAD)              // 68
#define SB_STRIDE (BN + PAD)              // 132
#define SA_BUF (BK * SA_STRIDE)           // 2176 floats
#define SB_BUF (BK * SB_STRIDE)           // 4224 floats
#define SMEM_FLOATS (2 * SA_BUF + 2 * SB_BUF)
#define SMEM_BYTES (SMEM_FLOATS * 4)      // 51200 B

// Scratch (static device globals; no dynamic allocation)
__device__ float g_pmin[B];
__device__ float g_pmax[B];
__device__ float g_coded[B * TWO_D];
__device__ float g_den[C];
__device__ float g_choice[B][C];   // numerator accumulated via REDG

// ---------------------------------------------------------------------------
// K1: per-batch-row min/max partials of x  +  zero g_choice row b
// (runs before k_choice, so the zeroing is ordered ahead of the atomics)
// ---------------------------------------------------------------------------
__global__ void k_minmax_partial(const float* __restrict__ x) {
    int b = blockIdx.x;
    int t = threadIdx.x;  // 128

    // zero this row of g_choice (2 float4 per thread)
    float4 z = make_float4(0.f, 0.f, 0.f, 0.f);
    ((float4*)&g_choice[b][0])[t] = z;
    ((float4*)&g_choice[b][0])[t + 128] = z;

    const float* row = x + b * DIN;
    float mn = 1e30f, mx = -1e30f;
    #pragma unroll
    for (int i = 0; i < 2; i++) {
        float4 v = ((const float4*)row)[t + i * 128];
        mn = fminf(mn, fminf(fminf(v.x, v.y), fminf(v.z, v.w)));
        mx = fmaxf(mx, fmaxf(fmaxf(v.x, v.y), fmaxf(v.z, v.w)));
    }
    #pragma unroll
    for (int o = 16; o > 0; o >>= 1) {
        mn = fminf(mn, __shfl_xor_sync(0xffffffffu, mn, o));
        mx = fmaxf(mx, __shfl_xor_sync(0xffffffffu, mx, o));
    }
    __shared__ float smn[4], smx[4];
    if ((t & 31) == 0) { smn[t >> 5] = mn; smx[t >> 5] = mx; }
    __syncthreads();
    if (t == 0) {
        mn = smn[0]; mx = smx[0];
        #pragma unroll
        for (int w = 1; w < 4; w++) { mn = fminf(mn, smn[w]); mx = fmaxf(mx, smx[w]); }
        g_pmin[b] = mn;
        g_pmax[b] = mx;
    }
}

// ---------------------------------------------------------------------------
// K2: blocks [0,C): den[c] = alpha + rowsum(T[c]) + gamma*counts[c]
//     blocks [C,C+B): final minmax reduce (local) + complement-coded rows
// ---------------------------------------------------------------------------
__global__ void k_prep(const float* __restrict__ x,
                       const float* __restrict__ T,
                       const int* __restrict__ counts) {
    int blk = blockIdx.x;
    int t = threadIdx.x;  // 256
    if (blk < C) {
        const float4* row = (const float4*)(T + (size_t)blk * TWO_D);
        float s = 0.0f;
        #pragma unroll
        for (int i = 0; i < 2; i++) {
            float4 v = row[t + i * 256];
            s += (v.x + v.y) + (v.z + v.w);
        }
        #pragma unroll
        for (int o = 16; o > 0; o >>= 1)
            s += __shfl_xor_sync(0xffffffffu, s, o);
        __shared__ float ss[8];
        if ((t & 31) == 0) ss[t >> 5] = s;
        __syncthreads();
        if (t == 0) {
            #pragma unroll
            for (int w = 1; w < 8; w++) s += ss[w];
            g_den[blk] = ALPHA + s + GAMMA * (float)counts[blk];
        }
    } else {
        int b = blk - C;
        __shared__ float smn[4], smx[4];
        float mn = 1e30f, mx = -1e30f;
        if (t < 128) {
            mn = g_pmin[t];
            mx = g_pmax[t];
            #pragma unroll
            for (int o = 16; o > 0; o >>= 1) {
                mn = fminf(mn, __shfl_xor_sync(0xffffffffu, mn, o));
                mx = fmaxf(mx, __shfl_xor_sync(0xffffffffu, mx, o));
            }
            if ((t & 31) == 0) { smn[t >> 5] = mn; smx[t >> 5] = mx; }
        }
        __syncthreads();
        mn = fminf(fminf(smn[0], smn[1]), fminf(smn[2], smn[3]));
        mx = fmaxf(fmaxf(smx[0], smx[1]), fmaxf(smx[2], smx[3]));
        float sc = 1.0f / (mx - mn + 1e-10f);

        const float* xr = x + (size_t)b * DIN;
        float* cr = g_coded + (size_t)b * TWO_D;
        #pragma unroll
        for (int i = 0; i < 4; i++) {
            int k = t + i * 256;
            float xn = (xr[k] - mn) * sc;
            cr[k] = xn;
            cr[DIN + k] = 1.0f - xn;
        }
    }
}

// ---------------------------------------------------------------------------
// K3: min-sum "GEMM". BM=64, BN=128, BK=32, 512 threads (32x16), TM=TN=4.
// grid = (8, 2, 8) = 128 CTAs = one wave, 4 warps/SMSP.
// Double-buffered dynamic smem, ONE __syncthreads per tile.
// Epilogue: REDG atomicAdd into g_choice (folds the K-split in place).
// ---------------------------------------------------------------------------
__global__ void __launch_bounds__(512) k_choice(const float* __restrict__ T) {
    extern __shared__ float sm[];
    float* sA = sm;                  // [2][BK][BM+PAD]
    float* sB = sm + 2 * SA_BUF;     // [2][BK][BN+PAD]

    int tid = threadIdx.x;
    int tx = tid & 31;       // n-group -> n0 = tx*4
    int ty = tid >> 5;       // m-group -> m0 = ty*4
    int mbase = blockIdx.y * BM;
    int nbase = blockIdx.x * BN;
    int k0 = blockIdx.z * KSLICE;

    int ra = tid >> 3;       // 0..63
    int kv = tid & 7;        // float4 index within BK

    const float4* pA  = (const float4*)&g_coded[(size_t)(mbase + ra) * TWO_D + k0 + kv * 4];
    const float4* pB0 = (const float4*)&T[(size_t)(nbase + ra) * TWO_D + k0 + kv * 4];
    const float4* pB1 = (const float4*)&T[(size_t)(nbase + ra + 64) * TWO_D + k0 + kv * 4];

    float acc[4][4];
    #pragma unroll
    for (int i = 0; i < 4; i++)
        #pragma unroll
        for (int j = 0; j < 4; j++) acc[i][j] = 0.0f;

    // prefetch + store tile 0 into buffer 0
    float4 va = pA[0], vb0 = pB0[0], vb1 = pB1[0];
    {
        int kc = kv * 4;
        float* a = sA + kc * SA_STRIDE;
        a[ra] = va.x; a[SA_STRIDE + ra] = va.y;
        a[2 * SA_STRIDE + ra] = va.z; a[3 * SA_STRIDE + ra] = va.w;
        float* bp = sB + kc * SB_STRIDE;
        bp[ra] = vb0.x; bp[SB_STRIDE + ra] = vb0.y;
        bp[2 * SB_STRIDE + ra] = vb0.z; bp[3 * SB_STRIDE + ra] = vb0.w;
        bp[ra + 64] = vb1.x; bp[SB_STRIDE + ra + 64] = vb1.y;
        bp[2 * SB_STRIDE + ra + 64] = vb1.z; bp[3 * SB_STRIDE + ra + 64] = vb1.w;
    }
    __syncthreads();

    int buf = 0;
    for (int tt = 0; tt < NT; tt++) {
        if (tt + 1 < NT) {   // prefetch next tile (overlaps compute below)
            int o = (tt + 1) * (BK / 4);
            va = pA[o]; vb0 = pB0[o]; vb1 = pB1[o];
        }
        const float* cA = sA + buf * SA_BUF + ty * 4;
        const float* cB = sB + buf * SB_BUF + tx * 4;
        #pragma unroll
        for (int k = 0; k < BK; k++) {
            float4 a = *(const float4*)(cA + k * SA_STRIDE);
            float4 bb = *(const float4*)(cB + k * SB_STRIDE);
            float av[4] = {a.x, a.y, a.z, a.w};
            float bv[4] = {bb.x, bb.y, bb.z, bb.w};
            #pragma unroll
            for (int i = 0; i < 4; i++)
                #pragma unroll
                for (int j = 0; j < 4; j++)
                    acc[i][j] += fminf(av[i], bv[j]);
        }
        if (tt + 1 < NT) {
            int nb = buf ^ 1;
            int kc = kv * 4;
            float* a = sA + nb * SA_BUF + kc * SA_STRIDE;
            a[ra] = va.x; a[SA_STRIDE + ra] = va.y;
            a[2 * SA_STRIDE + ra] = va.z; a[3 * SA_STRIDE + ra] = va.w;
            float* bp = sB + nb * SB_BUF + kc * SB_STRIDE;
            bp[ra] = vb0.x; bp[SB_STRIDE + ra] = vb0.y;
            bp[2 * SB_STRIDE + ra] = vb0.z; bp[3 * SB_STRIDE + ra] = vb0.w;
            bp[ra + 64] = vb1.x; bp[SB_STRIDE + ra + 64] = vb1.y;
            bp[2 * SB_STRIDE + ra + 64] = vb1.z; bp[3 * SB_STRIDE + ra + 64] = vb1.w;
            __syncthreads();
            buf = nb;
        }
    }

    // fire-and-forget reduction into g_choice (REDG, no return value used)
    int b0 = mbase + ty * 4;
    int c0 = nbase + tx * 4;
    #pragma unroll
    for (int i = 0; i < 4; i++)
        #pragma unroll
        for (int j = 0; j < 4; j++)
            atomicAdd(&g_choice[b0 + i][c0 + j], acc[i][j]);
}

// ---------------------------------------------------------------------------
// K4: per batch row (1024 threads, 1 category each): divide by den, masked
// argmax (first-index tie), per-label sums via per-warp smem rows, one-hot
// output. committed is int32.
// ---------------------------------------------------------------------------
__global__ void __launch_bounds__(1024) k_final(const int* __restrict__ committed,
                                                const int* __restrict__ labels,
                                                float* __restrict__ out) {
    int b = blockIdx.x;
    int t = threadIdx.x;        // 0..1023 == category index
    int lane = t & 31;
    int wid = t >> 5;
    __shared__ float sbins[32][NUM_CLASSES];
    __shared__ float bins[NUM_CLASSES];
    __shared__ float wval[32];
    __shared__ int widx[32];

    if (lane < NUM_CLASSES) sbins[wid][lane] = 0.0f;
    __syncthreads();

    float v = g_choice[b][t] / g_den[t];
    bool com = (committed[t] != 0);
    int lab = labels[t];
    if (com) atomicAdd(&sbins[wid][lab], v);

    // warp argmax, first-index on tie
    float best = com ? v : -INFINITY;
    int bidx = t;
    #pragma unroll
    for (int o = 16; o > 0; o >>= 1) {
        float ov = __shfl_xor_sync(0xffffffffu, best, o);
        int oi = __shfl_xor_sync(0xffffffffu, bidx, o);
        if (ov > best || (ov == best && oi < bidx)) { best = ov; bidx = oi; }
    }
    if (lane == 0) { wval[wid] = best; widx[wid] = bidx; }
    __syncthreads();

    if (wid == 0) {
        best = wval[lane];
        bidx = widx[lane];
        #pragma unroll
        for (int o = 16; o > 0; o >>= 1) {
            float ov = __shfl_xor_sync(0xffffffffu, best, o);
            int oi = __shfl_xor_sync(0xffffffffu, bidx, o);
            if (ov > best || (ov == best && oi < bidx)) { best = ov; bidx = oi; }
        }
        if (lane == 0) widx[0] = bidx;
    } else if (wid == 1 && lane < NUM_CLASSES) {
        float s = 0.0f;
        #pragma unroll
        for (int w = 0; w < 32; w++) s += sbins[w][lane];
        bins[lane] = s;
    }
    __syncthreads();

    if (t < NUM_CLASSES) {
        int pl = labels[widx[0]];
        out[b * NUM_CLASSES + t] = (t == pl) ? bins[t] : 0.0f;
    }
}

// ---------------------------------------------------------------------------
extern "C" void kernel_launch(void* const* d_in, const int* in_sizes, int n_in,
                              void* d_out, int out_size) {
    const float* x = (const float*)d_in[0];
    const float* T = (const float*)d_in[1];
    const int* committed = (const int*)d_in[2];
    const int* labels = (const int*)d_in[3];
    const int* counts = (const int*)d_in[4];
    float* out = (float*)d_out;

    cudaFuncSetAttribute(k_choice, cudaFuncAttributeMaxDynamicSharedMemorySize,
                         SMEM_BYTES);

    k_minmax_partial<<<B, 128>>>(x);
    k_prep<<<C + B, 256>>>(x, T, counts);
    dim3 g3(C / BN, B / BM, KSPLIT);
    k_choice<<<g3, 512, SMEM_BYTES>>>(T);
    k_final<<<B, 1024>>>(committed, labels, out);
}